// round 1
// baseline (speedup 1.0000x reference)
#include <cuda_runtime.h>
#include <cuda_bf16.h>
#include <cstdint>

// ============================================================================
// The 23-op resize chain is linear and separable: each op is A_k (H) ⊗ B_k (W).
// Composition: full = (A23...A1) ⊗ (B23...B1) = M_H (47x64) ⊗ M_W (30x64).
// So out_image = M_H @ X @ M_W^T for each of the 32*256 = 8192 planes.
//
// Kernel 1 (build_mats): builds M_H / M_W on device, replicating JAX float32
//   index math exactly. 128 blocks: (chain, column) — columns are independent
//   under row-combining ops, so each block pushes one column slice through all
//   23 ops in shared memory.
// Kernel 2 (resize_main): per-image 2-stage GEMM in smem with packed
//   fma.rn.f32x2 and LDS.128.
// ============================================================================

#define FFMA2(d, a, b, c) \
    asm("fma.rn.f32x2 %0, %1, %2, %3;" : "=l"(d) : "l"(a), "l"(b), "l"(c))
#define UNPACK_F32X2(lo, hi, v) \
    asm("mov.b64 {%0, %1}, %2;" : "=f"(lo), "=f"(hi) : "l"(v))

struct ResOp {
    int out;    // output size along this dim
    int mode;   // 0 = nearest, 1 = bilinear, 2 = bicubic
    int align;  // align_corners
    float r;    // precomputed f32 ratio: in/out (or (in-1)/(out-1) if align)
};

// H chain: 64->16->32->20->80->16->32 ->16->32->20->80->16->32
//          ->16->32->20->80->16->32 ->54->108->54->43->47
__constant__ ResOp H_OPS[23] = {
    {16, 0, 0, (float)(64.0 / 16.0)},
    {32, 0, 0, (float)(16.0 / 32.0)},
    {20, 0, 0, (float)(32.0 / 20.0)},
    {80, 0, 0, (float)(20.0 / 80.0)},
    {16, 0, 0, (float)(80.0 / 16.0)},
    {32, 0, 0, (float)(16.0 / 32.0)},
    {16, 1, 0, (float)(32.0 / 16.0)},
    {32, 1, 0, (float)(16.0 / 32.0)},
    {20, 1, 0, (float)(32.0 / 20.0)},
    {80, 1, 0, (float)(20.0 / 80.0)},
    {16, 1, 1, (float)(79.0 / 15.0)},
    {32, 1, 1, (float)(15.0 / 31.0)},
    {16, 2, 0, (float)(32.0 / 16.0)},
    {32, 2, 0, (float)(16.0 / 32.0)},
    {20, 2, 0, (float)(32.0 / 20.0)},
    {80, 2, 0, (float)(20.0 / 80.0)},
    {16, 2, 1, (float)(79.0 / 15.0)},
    {32, 2, 1, (float)(15.0 / 31.0)},
    {54, 0, 0, (float)(32.0 / 54.0)},
    {108, 1, 0, (float)(54.0 / 108.0)},
    {54, 1, 1, (float)(107.0 / 53.0)},
    {43, 2, 0, (float)(54.0 / 43.0)},
    {47, 2, 1, (float)(42.0 / 46.0)},
};

// W chain: 64->16->32->20->80->24->72 ->16->32->20->80->24->72
//          ->16->32->20->80->24->72 ->144->172->68->61->30
__constant__ ResOp W_OPS[23] = {
    {16, 0, 0, (float)(64.0 / 16.0)},
    {32, 0, 0, (float)(16.0 / 32.0)},
    {20, 0, 0, (float)(32.0 / 20.0)},
    {80, 0, 0, (float)(20.0 / 80.0)},
    {24, 0, 0, (float)(80.0 / 24.0)},
    {72, 0, 0, (float)(24.0 / 72.0)},
    {16, 1, 0, (float)(72.0 / 16.0)},
    {32, 1, 0, (float)(16.0 / 32.0)},
    {20, 1, 0, (float)(32.0 / 20.0)},
    {80, 1, 0, (float)(20.0 / 80.0)},
    {24, 1, 1, (float)(79.0 / 23.0)},
    {72, 1, 1, (float)(23.0 / 71.0)},
    {16, 2, 0, (float)(72.0 / 16.0)},
    {32, 2, 0, (float)(16.0 / 32.0)},
    {20, 2, 0, (float)(32.0 / 20.0)},
    {80, 2, 0, (float)(20.0 / 80.0)},
    {24, 2, 1, (float)(79.0 / 23.0)},
    {72, 2, 1, (float)(23.0 / 71.0)},
    {144, 0, 0, (float)(72.0 / 144.0)},
    {172, 1, 0, (float)(144.0 / 172.0)},
    {68, 1, 1, (float)(171.0 / 67.0)},
    {61, 2, 0, (float)(68.0 / 61.0)},
    {30, 2, 1, (float)(60.0 / 29.0)},
};

__device__ float g_MH[47 * 64];  // final H matrix (47 x 64)
__device__ float g_MW[30 * 64];  // final W matrix (30 x 64)

__device__ __forceinline__ float cc1(float t) {
    // ((A+2)*t - (A+3))*t*t + 1, A = -0.75
    return ((1.25f * t - 2.25f) * t) * t + 1.0f;
}
__device__ __forceinline__ float cc2(float t) {
    // ((A*t - 5A)*t + 8A)*t - 4A, A = -0.75
    return (((-0.75f) * t + 3.75f) * t - 6.0f) * t + 3.0f;
}

__device__ __forceinline__ int clampi(int v, int lo, int hi) {
    return v < lo ? lo : (v > hi ? hi : v);
}

// One block per (chain, column). Pushes a single 64-entry basis column through
// all 23 1D resizes. Max intermediate length: 172 (W chain).
__global__ void build_mats() {
    const int col = blockIdx.x & 63;
    const int chain = blockIdx.x >> 6;  // 0 = H, 1 = W
    __shared__ float bufA[172];
    __shared__ float bufB[172];
    float* bufs[2] = {bufA, bufB};

    const int t = threadIdx.x;
    if (t < 64) bufA[t] = (t == col) ? 1.0f : 0.0f;
    __syncthreads();

    int cur = 0;
    int in = 64;
    for (int o = 0; o < 23; o++) {
        ResOp op = chain ? W_OPS[o] : H_OPS[o];
        const float* src = bufs[cur];
        float* dst = bufs[cur ^ 1];
        if (t < op.out) {
            float d = (float)t;
            float v;
            if (op.mode == 0) {
                // nearest: idx = min(floor(d * in/out), in-1); f32 mul exact like JAX
                int id = (int)floorf(__fmul_rn(d, op.r));
                if (id > in - 1) id = in - 1;
                v = src[id];
            } else {
                float s;
                if (op.align) {
                    s = __fmul_rn(d, op.r);
                } else {
                    // (d + 0.5) * (in/out) - 0.5, no FMA contraction
                    s = __fadd_rn(__fmul_rn(__fadd_rn(d, 0.5f), op.r), -0.5f);
                    if (op.mode == 1) s = fmaxf(s, 0.0f);
                }
                float x0 = floorf(s);
                int i0 = (int)x0;
                float tt = __fadd_rn(s, -x0);
                if (op.mode == 1) {
                    int i1 = i0 + 1;
                    if (i1 > in - 1) i1 = in - 1;
                    v = (1.0f - tt) * src[i0] + tt * src[i1];
                } else {
                    float w0 = cc2(tt + 1.0f);
                    float w1 = cc1(tt);
                    float w2 = cc1(1.0f - tt);
                    float w3 = cc2(2.0f - tt);
                    int ia = clampi(i0 - 1, 0, in - 1);
                    int ib = clampi(i0, 0, in - 1);
                    int ic = clampi(i0 + 1, 0, in - 1);
                    int ie = clampi(i0 + 2, 0, in - 1);
                    v = w0 * src[ia] + w1 * src[ib] + w2 * src[ic] + w3 * src[ie];
                }
            }
            dst[t] = v;
        }
        __syncthreads();
        cur ^= 1;
        in = op.out;
    }

    const float* fin = bufs[cur];
    const int rows = chain ? 30 : 47;
    if (t < rows) {
        if (chain)
            g_MW[t * 64 + col] = fin[t];
        else
            g_MH[t * 64 + col] = fin[t];
    }
}

// ============================================================================
// Main kernel: one block per image plane (8192 planes), 256 threads = 8 warps.
// Stage 1: T[j][h] = sum_w X[h][w] * MW[j][w]   (64x30)
// Stage 2: O[i][j] = sum_h MH[i][h] * T[j][h]   (47x30)
// lane j (0..29) owns output column j; warp wg owns h/i residues (wg + 8k).
// Packed f32x2 FMAs; lane-distinct smem rows padded to 68 floats (68 % 32 = 4,
// 16B-aligned) so LDS.128 is throughput-optimal; warp-uniform reads broadcast.
// ============================================================================
__global__ __launch_bounds__(256) void resize_main(const float* __restrict__ x,
                                                   float* __restrict__ out) {
    __shared__ __align__(16) float Xs[64 * 64];   // 16384 B
    __shared__ __align__(16) float MWs[30 * 68];  //  8160 B (padded rows)
    __shared__ __align__(16) float MHs[48 * 64];  // 12288 B (row 47 zero pad)
    __shared__ __align__(16) float Ts[30 * 68];   //  8160 B (padded rows)

    const int t = threadIdx.x;
    const int b = blockIdx.x;

    // Load X plane (4096 floats) vectorized.
    {
        const float4* src = (const float4*)(x + (size_t)b * 4096);
        float4* dst = (float4*)Xs;
#pragma unroll
        for (int k = 0; k < 4; k++) dst[t + 256 * k] = src[t + 256 * k];
    }
    // Load MW into padded rows, MH dense.
    for (int k = t; k < 30 * 64; k += 256) MWs[(k >> 6) * 68 + (k & 63)] = g_MW[k];
    for (int k = t; k < 47 * 64; k += 256) MHs[k] = g_MH[k];
    if (t < 64) MHs[47 * 64 + t] = 0.0f;
    __syncthreads();

    const int j = t & 31;
    const int wg = t >> 5;

    // ---- Stage 1 ----
    if (j < 30) {
        unsigned long long acc[8][2];
#pragma unroll
        for (int k = 0; k < 8; k++) { acc[k][0] = 0ull; acc[k][1] = 0ull; }
        const ulonglong2* mwrow = (const ulonglong2*)&MWs[j * 68];
#pragma unroll 4
        for (int w4 = 0; w4 < 16; w4++) {
            ulonglong2 mw = mwrow[w4];  // MW[j][4w4 .. 4w4+3], lane-distinct
#pragma unroll
            for (int k = 0; k < 8; k++) {
                const int h = wg + 8 * k;
                ulonglong2 xv = *(const ulonglong2*)&Xs[h * 64 + w4 * 4];  // broadcast
                FFMA2(acc[k][0], xv.x, mw.x, acc[k][0]);
                FFMA2(acc[k][1], xv.y, mw.y, acc[k][1]);
            }
        }
#pragma unroll
        for (int k = 0; k < 8; k++) {
            float a0, a1, a2, a3;
            UNPACK_F32X2(a0, a1, acc[k][0]);
            UNPACK_F32X2(a2, a3, acc[k][1]);
            Ts[j * 68 + wg + 8 * k] = (a0 + a1) + (a2 + a3);
        }
    }
    __syncthreads();

    // ---- Stage 2 ----
    if (j < 30) {
        unsigned long long acc[6][2];
#pragma unroll
        for (int k = 0; k < 6; k++) { acc[k][0] = 0ull; acc[k][1] = 0ull; }
        const ulonglong2* trow = (const ulonglong2*)&Ts[j * 68];
#pragma unroll 4
        for (int h4 = 0; h4 < 16; h4++) {
            ulonglong2 tv = trow[h4];  // T[j][4h4 .. 4h4+3], lane-distinct
#pragma unroll
            for (int k = 0; k < 6; k++) {
                const int i = wg + 8 * k;  // i == 47 hits the zero pad row
                ulonglong2 mh = *(const ulonglong2*)&MHs[i * 64 + h4 * 4];  // broadcast
                FFMA2(acc[k][0], mh.x, tv.x, acc[k][0]);
                FFMA2(acc[k][1], mh.y, tv.y, acc[k][1]);
            }
        }
        float* O = out + (size_t)b * 1410;
#pragma unroll
        for (int k = 0; k < 6; k++) {
            const int i = wg + 8 * k;
            if (i < 47) {
                float a0, a1, a2, a3;
                UNPACK_F32X2(a0, a1, acc[k][0]);
                UNPACK_F32X2(a2, a3, acc[k][1]);
                O[i * 30 + j] = (a0 + a1) + (a2 + a3);
            }
        }
    }
}

extern "C" void kernel_launch(void* const* d_in, const int* in_sizes, int n_in,
                              void* d_out, int out_size) {
    const float* x = (const float*)d_in[0];
    float* out = (float*)d_out;
    (void)in_sizes; (void)n_in; (void)out_size;

    build_mats<<<128, 192>>>();
    resize_main<<<8192, 256>>>(x, out);
}

// round 2
// speedup vs baseline: 1.0015x; 1.0015x over previous
#include <cuda_runtime.h>
#include <cuda_bf16.h>
#include <cstdint>

// ============================================================================
// The 23-op resize chain is linear and separable: each op is A_k (H) ⊗ B_k (W).
// Composition: full = (A23...A1) ⊗ (B23...B1) = M_H (47x64) ⊗ M_W (30x64).
// So out_image = M_H @ X @ M_W^T for each of the 32*256 = 8192 planes.
//
// Kernel 1 (build_mats): builds M_H / M_W on device, replicating JAX float32
//   index math exactly. 128 blocks: (chain, column) — columns are independent
//   under row-combining ops, so each block pushes one column slice through all
//   23 ops in shared memory.
// Kernel 2 (resize_main): per-image 2-stage GEMM in smem with packed
//   fma.rn.f32x2 and LDS.128.
// ============================================================================

#define FFMA2(d, a, b, c) \
    asm("fma.rn.f32x2 %0, %1, %2, %3;" : "=l"(d) : "l"(a), "l"(b), "l"(c))
#define UNPACK_F32X2(lo, hi, v) \
    asm("mov.b64 {%0, %1}, %2;" : "=f"(lo), "=f"(hi) : "l"(v))

struct ResOp {
    int out;    // output size along this dim
    int mode;   // 0 = nearest, 1 = bilinear, 2 = bicubic
    int align;  // align_corners
    float r;    // precomputed f32 ratio: in/out (or (in-1)/(out-1) if align)
};

// H chain: 64->16->32->20->80->16->32 ->16->32->20->80->16->32
//          ->16->32->20->80->16->32 ->54->108->54->43->47
__constant__ ResOp H_OPS[23] = {
    {16, 0, 0, (float)(64.0 / 16.0)},
    {32, 0, 0, (float)(16.0 / 32.0)},
    {20, 0, 0, (float)(32.0 / 20.0)},
    {80, 0, 0, (float)(20.0 / 80.0)},
    {16, 0, 0, (float)(80.0 / 16.0)},
    {32, 0, 0, (float)(16.0 / 32.0)},
    {16, 1, 0, (float)(32.0 / 16.0)},
    {32, 1, 0, (float)(16.0 / 32.0)},
    {20, 1, 0, (float)(32.0 / 20.0)},
    {80, 1, 0, (float)(20.0 / 80.0)},
    {16, 1, 1, (float)(79.0 / 15.0)},
    {32, 1, 1, (float)(15.0 / 31.0)},
    {16, 2, 0, (float)(32.0 / 16.0)},
    {32, 2, 0, (float)(16.0 / 32.0)},
    {20, 2, 0, (float)(32.0 / 20.0)},
    {80, 2, 0, (float)(20.0 / 80.0)},
    {16, 2, 1, (float)(79.0 / 15.0)},
    {32, 2, 1, (float)(15.0 / 31.0)},
    {54, 0, 0, (float)(32.0 / 54.0)},
    {108, 1, 0, (float)(54.0 / 108.0)},
    {54, 1, 1, (float)(107.0 / 53.0)},
    {43, 2, 0, (float)(54.0 / 43.0)},
    {47, 2, 1, (float)(42.0 / 46.0)},
};

// W chain: 64->16->32->20->80->24->72 ->16->32->20->80->24->72
//          ->16->32->20->80->24->72 ->144->172->68->61->30
__constant__ ResOp W_OPS[23] = {
    {16, 0, 0, (float)(64.0 / 16.0)},
    {32, 0, 0, (float)(16.0 / 32.0)},
    {20, 0, 0, (float)(32.0 / 20.0)},
    {80, 0, 0, (float)(20.0 / 80.0)},
    {24, 0, 0, (float)(80.0 / 24.0)},
    {72, 0, 0, (float)(24.0 / 72.0)},
    {16, 1, 0, (float)(72.0 / 16.0)},
    {32, 1, 0, (float)(16.0 / 32.0)},
    {20, 1, 0, (float)(32.0 / 20.0)},
    {80, 1, 0, (float)(20.0 / 80.0)},
    {24, 1, 1, (float)(79.0 / 23.0)},
    {72, 1, 1, (float)(23.0 / 71.0)},
    {16, 2, 0, (float)(72.0 / 16.0)},
    {32, 2, 0, (float)(16.0 / 32.0)},
    {20, 2, 0, (float)(32.0 / 20.0)},
    {80, 2, 0, (float)(20.0 / 80.0)},
    {24, 2, 1, (float)(79.0 / 23.0)},
    {72, 2, 1, (float)(23.0 / 71.0)},
    {144, 0, 0, (float)(72.0 / 144.0)},
    {172, 1, 0, (float)(144.0 / 172.0)},
    {68, 1, 1, (float)(171.0 / 67.0)},
    {61, 2, 0, (float)(68.0 / 61.0)},
    {30, 2, 1, (float)(60.0 / 29.0)},
};

__device__ float g_MH[47 * 64];  // final H matrix (47 x 64)
__device__ float g_MW[30 * 64];  // final W matrix (30 x 64)

__device__ __forceinline__ float cc1(float t) {
    // ((A+2)*t - (A+3))*t*t + 1, A = -0.75
    return ((1.25f * t - 2.25f) * t) * t + 1.0f;
}
__device__ __forceinline__ float cc2(float t) {
    // ((A*t - 5A)*t + 8A)*t - 4A, A = -0.75
    return (((-0.75f) * t + 3.75f) * t - 6.0f) * t + 3.0f;
}

__device__ __forceinline__ int clampi(int v, int lo, int hi) {
    return v < lo ? lo : (v > hi ? hi : v);
}

// One block per (chain, column). Pushes a single 64-entry basis column through
// all 23 1D resizes. Max intermediate length: 172 (W chain).
__global__ void build_mats() {
    const int col = blockIdx.x & 63;
    const int chain = blockIdx.x >> 6;  // 0 = H, 1 = W
    __shared__ float bufA[172];
    __shared__ float bufB[172];
    float* bufs[2] = {bufA, bufB};

    const int t = threadIdx.x;
    if (t < 64) bufA[t] = (t == col) ? 1.0f : 0.0f;
    __syncthreads();

    int cur = 0;
    int in = 64;
    for (int o = 0; o < 23; o++) {
        ResOp op = chain ? W_OPS[o] : H_OPS[o];
        const float* src = bufs[cur];
        float* dst = bufs[cur ^ 1];
        if (t < op.out) {
            float d = (float)t;
            float v;
            if (op.mode == 0) {
                // nearest: idx = min(floor(d * in/out), in-1); f32 mul exact like JAX
                int id = (int)floorf(__fmul_rn(d, op.r));
                if (id > in - 1) id = in - 1;
                v = src[id];
            } else {
                float s;
                if (op.align) {
                    s = __fmul_rn(d, op.r);
                } else {
                    // (d + 0.5) * (in/out) - 0.5, no FMA contraction
                    s = __fadd_rn(__fmul_rn(__fadd_rn(d, 0.5f), op.r), -0.5f);
                    if (op.mode == 1) s = fmaxf(s, 0.0f);
                }
                float x0 = floorf(s);
                int i0 = (int)x0;
                float tt = __fadd_rn(s, -x0);
                if (op.mode == 1) {
                    int i1 = i0 + 1;
                    if (i1 > in - 1) i1 = in - 1;
                    v = (1.0f - tt) * src[i0] + tt * src[i1];
                } else {
                    float w0 = cc2(tt + 1.0f);
                    float w1 = cc1(tt);
                    float w2 = cc1(1.0f - tt);
                    float w3 = cc2(2.0f - tt);
                    int ia = clampi(i0 - 1, 0, in - 1);
                    int ib = clampi(i0, 0, in - 1);
                    int ic = clampi(i0 + 1, 0, in - 1);
                    int ie = clampi(i0 + 2, 0, in - 1);
                    v = w0 * src[ia] + w1 * src[ib] + w2 * src[ic] + w3 * src[ie];
                }
            }
            dst[t] = v;
        }
        __syncthreads();
        cur ^= 1;
        in = op.out;
    }

    const float* fin = bufs[cur];
    const int rows = chain ? 30 : 47;
    if (t < rows) {
        if (chain)
            g_MW[t * 64 + col] = fin[t];
        else
            g_MH[t * 64 + col] = fin[t];
    }
}

// ============================================================================
// Main kernel: one block per image plane (8192 planes), 256 threads = 8 warps.
// Stage 1: T[j][h] = sum_w X[h][w] * MW[j][w]   (64x30)
// Stage 2: O[i][j] = sum_h MH[i][h] * T[j][h]   (47x30)
// lane j (0..29) owns output column j; warp wg owns h/i residues (wg + 8k).
// Packed f32x2 FMAs; lane-distinct smem rows padded to 68 floats (68 % 32 = 4,
// 16B-aligned) so LDS.128 is throughput-optimal; warp-uniform reads broadcast.
// ============================================================================
__global__ __launch_bounds__(256) void resize_main(const float* __restrict__ x,
                                                   float* __restrict__ out) {
    __shared__ __align__(16) float Xs[64 * 64];   // 16384 B
    __shared__ __align__(16) float MWs[30 * 68];  //  8160 B (padded rows)
    __shared__ __align__(16) float MHs[48 * 64];  // 12288 B (row 47 zero pad)
    __shared__ __align__(16) float Ts[30 * 68];   //  8160 B (padded rows)

    const int t = threadIdx.x;
    const int b = blockIdx.x;

    // Load X plane (4096 floats) vectorized.
    {
        const float4* src = (const float4*)(x + (size_t)b * 4096);
        float4* dst = (float4*)Xs;
#pragma unroll
        for (int k = 0; k < 4; k++) dst[t + 256 * k] = src[t + 256 * k];
    }
    // Load MW into padded rows, MH dense.
    for (int k = t; k < 30 * 64; k += 256) MWs[(k >> 6) * 68 + (k & 63)] = g_MW[k];
    for (int k = t; k < 47 * 64; k += 256) MHs[k] = g_MH[k];
    if (t < 64) MHs[47 * 64 + t] = 0.0f;
    __syncthreads();

    const int j = t & 31;
    const int wg = t >> 5;

    // ---- Stage 1 ----
    if (j < 30) {
        unsigned long long acc[8][2];
#pragma unroll
        for (int k = 0; k < 8; k++) { acc[k][0] = 0ull; acc[k][1] = 0ull; }
        const ulonglong2* mwrow = (const ulonglong2*)&MWs[j * 68];
#pragma unroll 4
        for (int w4 = 0; w4 < 16; w4++) {
            ulonglong2 mw = mwrow[w4];  // MW[j][4w4 .. 4w4+3], lane-distinct
#pragma unroll
            for (int k = 0; k < 8; k++) {
                const int h = wg + 8 * k;
                ulonglong2 xv = *(const ulonglong2*)&Xs[h * 64 + w4 * 4];  // broadcast
                FFMA2(acc[k][0], xv.x, mw.x, acc[k][0]);
                FFMA2(acc[k][1], xv.y, mw.y, acc[k][1]);
            }
        }
#pragma unroll
        for (int k = 0; k < 8; k++) {
            float a0, a1, a2, a3;
            UNPACK_F32X2(a0, a1, acc[k][0]);
            UNPACK_F32X2(a2, a3, acc[k][1]);
            Ts[j * 68 + wg + 8 * k] = (a0 + a1) + (a2 + a3);
        }
    }
    __syncthreads();

    // ---- Stage 2 ----
    if (j < 30) {
        unsigned long long acc[6][2];
#pragma unroll
        for (int k = 0; k < 6; k++) { acc[k][0] = 0ull; acc[k][1] = 0ull; }
        const ulonglong2* trow = (const ulonglong2*)&Ts[j * 68];
#pragma unroll 4
        for (int h4 = 0; h4 < 16; h4++) {
            ulonglong2 tv = trow[h4];  // T[j][4h4 .. 4h4+3], lane-distinct
#pragma unroll
            for (int k = 0; k < 6; k++) {
                const int i = wg + 8 * k;  // i == 47 hits the zero pad row
                ulonglong2 mh = *(const ulonglong2*)&MHs[i * 64 + h4 * 4];  // broadcast
                FFMA2(acc[k][0], mh.x, tv.x, acc[k][0]);
                FFMA2(acc[k][1], mh.y, tv.y, acc[k][1]);
            }
        }
        float* O = out + (size_t)b * 1410;
#pragma unroll
        for (int k = 0; k < 6; k++) {
            const int i = wg + 8 * k;
            if (i < 47) {
                float a0, a1, a2, a3;
                UNPACK_F32X2(a0, a1, acc[k][0]);
                UNPACK_F32X2(a2, a3, acc[k][1]);
                O[i * 30 + j] = (a0 + a1) + (a2 + a3);
            }
        }
    }
}

extern "C" void kernel_launch(void* const* d_in, const int* in_sizes, int n_in,
                              void* d_out, int out_size) {
    const float* x = (const float*)d_in[0];
    float* out = (float*)d_out;
    (void)in_sizes; (void)n_in; (void)out_size;

    build_mats<<<128, 192>>>();
    resize_main<<<8192, 256>>>(x, out);
}

// round 12
// speedup vs baseline: 1.4311x; 1.4289x over previous
#include <cuda_runtime.h>
#include <cuda_bf16.h>
#include <cstdint>

// ============================================================================
// Chain is linear/separable: Y = M_H(47x64) · X · M_W^T(64x30) per plane.
// W-side rank-16 split: M_W = U_W(30x16) · V_W(16x64). Keep the 16-wide
// dimension as long as possible:
//   A:  T1 = X · V_W^T      (64x16, red 64)   65.5K FMA
//   B': T2 = M_H · T1       (47x16, red 64)   48.1K FMA
//   C': Y  = T2 · U_W^T     (47x30, red 16)   22.6K FMA
// 136K FMA/plane (vs 213K unfactored), every stage register-tiled at
// >=2.4 FFMA2 per LDS wavefront.
// ============================================================================

#define FFMA2(d,a,b,c) asm("fma.rn.f32x2 %0, %1, %2, %3;" : "=l"(d) : "l"(a),"l"(b),"l"(c))
#define PACKDUP(d,v)   asm("mov.b64 %0, {%1, %1};" : "=l"(d) : "f"(v))
#define UNPACK2(lo,hi,v) asm("mov.b64 {%0, %1}, %2;" : "=f"(lo),"=f"(hi) : "l"(v))
typedef unsigned long long ull;

struct ResOp { int out, mode, align; float r; };  // mode: 0 nearest,1 bilinear,2 bicubic

__constant__ ResOp H_OPS[23] = {
    {16,0,0,(float)(64.0/16.0)},  {32,0,0,(float)(16.0/32.0)},
    {20,0,0,(float)(32.0/20.0)},  {80,0,0,(float)(20.0/80.0)},
    {16,0,0,(float)(80.0/16.0)},  {32,0,0,(float)(16.0/32.0)},
    {16,1,0,(float)(32.0/16.0)},  {32,1,0,(float)(16.0/32.0)},
    {20,1,0,(float)(32.0/20.0)},  {80,1,0,(float)(20.0/80.0)},
    {16,1,1,(float)(79.0/15.0)},  {32,1,1,(float)(15.0/31.0)},
    {16,2,0,(float)(32.0/16.0)},  {32,2,0,(float)(16.0/32.0)},
    {20,2,0,(float)(32.0/20.0)},  {80,2,0,(float)(20.0/80.0)},
    {16,2,1,(float)(79.0/15.0)},  {32,2,1,(float)(15.0/31.0)},
    {54,0,0,(float)(32.0/54.0)},  {108,1,0,(float)(54.0/108.0)},
    {54,1,1,(float)(107.0/53.0)}, {43,2,0,(float)(54.0/43.0)},
    {47,2,1,(float)(42.0/46.0)},
};
__constant__ ResOp W_OPS[23] = {
    {16,0,0,(float)(64.0/16.0)},  {32,0,0,(float)(16.0/32.0)},
    {20,0,0,(float)(32.0/20.0)},  {80,0,0,(float)(20.0/80.0)},
    {24,0,0,(float)(80.0/24.0)},  {72,0,0,(float)(24.0/72.0)},
    {16,1,0,(float)(72.0/16.0)},  {32,1,0,(float)(16.0/32.0)},
    {20,1,0,(float)(32.0/20.0)},  {80,1,0,(float)(20.0/80.0)},
    {24,1,1,(float)(79.0/23.0)},  {72,1,1,(float)(23.0/71.0)},
    {16,2,0,(float)(72.0/16.0)},  {32,2,0,(float)(16.0/32.0)},
    {20,2,0,(float)(32.0/20.0)},  {80,2,0,(float)(20.0/80.0)},
    {24,2,1,(float)(79.0/23.0)},  {72,2,1,(float)(23.0/71.0)},
    {144,0,0,(float)(72.0/144.0)},{172,1,0,(float)(144.0/172.0)},
    {68,1,1,(float)(171.0/67.0)}, {61,2,0,(float)(68.0/61.0)},
    {30,2,1,(float)(60.0/29.0)},
};

// g_MHt[h*48+i] = M_H[i][h] (full H chain, transposed; col i=47 zero)
// g_VW [c*68+w] = V_W[c][w] (W ops 0..12; rows padded to 68)
// g_UWT[c*32+j] = U_W[j][c] (W ops 13..22, transposed; j>=30 zero)
__device__ __align__(16) float g_MHt[64*48];
__device__ __align__(16) float g_VW [16*68];
__device__ __align__(16) float g_UWT[16*32];

__device__ __forceinline__ float cc1(float t){ return ((1.25f*t - 2.25f)*t)*t + 1.0f; }
__device__ __forceinline__ float cc2(float t){ return (((-0.75f)*t + 3.75f)*t - 6.0f)*t + 3.0f; }
__device__ __forceinline__ int clampi(int v,int lo,int hi){ return v<lo?lo:(v>hi?hi:v); }

// 144 blocks: 0..63 full-H col, 64..127 V_W col, 128..143 U_W col.
__global__ void build_mats() {
    const int bid = blockIdx.x;
    int kind, start, count, insz, col;
    if (bid < 64)       { kind=0; start=0;  count=23; insz=64; col=bid; }
    else if (bid < 128) { kind=1; start=0;  count=13; insz=64; col=bid-64; }
    else                { kind=2; start=13; count=10; insz=16; col=bid-128; }

    __shared__ float bufA[172], bufB[172];
    float* bufs[2] = {bufA, bufB};
    const int t = threadIdx.x;
    if (t < insz) bufA[t] = (t == col) ? 1.0f : 0.0f;
    __syncthreads();

    int cur = 0, in = insz;
    for (int o = start; o < start+count; o++) {
        ResOp op = (kind==0) ? H_OPS[o] : W_OPS[o];
        const float* src = bufs[cur];
        float* dst = bufs[cur^1];
        if (t < op.out) {
            float d = (float)t, v;
            if (op.mode == 0) {
                int id = (int)floorf(__fmul_rn(d, op.r));
                if (id > in-1) id = in-1;
                v = src[id];
            } else {
                float s;
                if (op.align) s = __fmul_rn(d, op.r);
                else {
                    s = __fadd_rn(__fmul_rn(__fadd_rn(d, 0.5f), op.r), -0.5f);
                    if (op.mode == 1) s = fmaxf(s, 0.0f);
                }
                float x0 = floorf(s);
                int i0 = (int)x0;
                float tt = __fadd_rn(s, -x0);
                if (op.mode == 1) {
                    int i1 = i0+1; if (i1 > in-1) i1 = in-1;
                    v = (1.0f-tt)*src[i0] + tt*src[i1];
                } else {
                    float w0=cc2(tt+1.0f), w1=cc1(tt), w2=cc1(1.0f-tt), w3=cc2(2.0f-tt);
                    v = w0*src[clampi(i0-1,0,in-1)] + w1*src[clampi(i0,0,in-1)]
                      + w2*src[clampi(i0+1,0,in-1)] + w3*src[clampi(i0+2,0,in-1)];
                }
            }
            dst[t] = v;
        }
        __syncthreads();
        cur ^= 1; in = op.out;
    }

    const float* fin = bufs[cur];
    if (kind == 0) {            // full M_H: 47 rows; store transposed, pad i=47
        if (t < 48) g_MHt[col*48 + t] = (t < 47) ? fin[t] : 0.0f;
    } else if (kind == 1) {     // V_W: 16 rows
        if (t < 16) g_VW[t*68 + col] = fin[t];
    } else {                    // U_W: 30 rows; transposed, pad j 30,31
        if (t < 32) g_UWT[col*32 + t] = (t < 30) ? fin[t] : 0.0f;
    }
}

// ----------------------------------------------------------------------------
// Main: 2048 blocks x 256 threads, 4 planes per block, 2 warps per plane.
// Dynamic smem (floats):
//   Xs  [4][64][68]  @0      17408   (stage A input; dead after stage A)
//   T1s [4][64][17]  @17408   4352   (A out / B' in)
//   VWs [16][68]     @21760   1088
//   UWTs[16][32]     @22848    512
//   MHs [64][48]     @23360   3072
//   T2s [4][48][17]  @0       3264   (B' out / C' in; aliases dead Xs)
// total 26432 floats = 105728 B -> 2 CTAs/SM.
// Warp w: plane p=w>>1, half=w&1. lane: l8=lane&7, l4=lane>>3.
// ----------------------------------------------------------------------------
__global__ __launch_bounds__(256, 2) void resize_main(const float* __restrict__ x,
                                                      float* __restrict__ out) {
    extern __shared__ __align__(16) float sm[];
    float* Xs   = sm;
    float* T1s  = sm + 17408;
    float* VWs  = sm + 21760;
    float* UWTs = sm + 22848;
    float* MHs  = sm + 23360;
    float* T2s  = sm;  // alias Xs (dead after stage A sync)

    const int t = threadIdx.x;

    // ---- stage X + matrices into smem ----
    {
        const float4* xv = (const float4*)(x + (size_t)blockIdx.x * 4 * 4096);
#pragma unroll
        for (int k = 0; k < 16; k++) {
            int g = t + 256*k;               // 0..4095 float4s
            float4 v = xv[g];
            int p = g >> 10, r = g & 1023, h = r >> 4, q = r & 15;
            *(float4*)&Xs[p*4352 + h*68 + q*4] = v;
        }
        for (int k = t; k < 1088; k += 256) VWs[k]  = g_VW[k];
        for (int k = t; k < 512;  k += 256) UWTs[k] = g_UWT[k];
        for (int k = t; k < 3072; k += 256) MHs[k]  = g_MHt[k];
    }
    __syncthreads();

    const int lane = t & 31, w = t >> 5;
    const int p = w >> 1, half = w & 1;
    const int l8 = lane & 7, l4 = lane >> 3;

    // ---- Stage A: T1[h][c] = sum_w X[h][w] * V_W[c][w] ----
    // thread tile: 4 h (half*32 + l8 + 8k) x 4 c (l4 + 4cj); f32x2 pack w parity.
    {
        ull accA[4][4];
#pragma unroll
        for (int k = 0; k < 4; k++)
#pragma unroll
            for (int c = 0; c < 4; c++) accA[k][c] = 0ull;
        const float* Xp = Xs + p*4352 + half*32*68;
#pragma unroll 2
        for (int wq = 0; wq < 16; wq++) {
            ulonglong2 vw[4];
#pragma unroll
            for (int cj = 0; cj < 4; cj++)
                vw[cj] = *(const ulonglong2*)&VWs[(l4 + 4*cj)*68 + wq*4];
#pragma unroll
            for (int k = 0; k < 4; k++) {
                ulonglong2 xvv = *(const ulonglong2*)&Xp[(l8 + 8*k)*68 + wq*4];
#pragma unroll
                for (int cj = 0; cj < 4; cj++) {
                    FFMA2(accA[k][cj], xvv.x, vw[cj].x, accA[k][cj]);
                    FFMA2(accA[k][cj], xvv.y, vw[cj].y, accA[k][cj]);
                }
            }
        }
#pragma unroll
        for (int k = 0; k < 4; k++)
#pragma unroll
            for (int cj = 0; cj < 4; cj++) {
                float lo, hi; UNPACK2(lo, hi, accA[k][cj]);
                T1s[p*1088 + (half*32 + l8 + 8*k)*17 + (l4 + 4*cj)] = lo + hi;
            }
    }
    __syncthreads();   // T1 ready; Xs dead -> T2s may be written

    // ---- Stage B': T2[i][c] = sum_h M_H[i][h] * T1[h][c] ----
    // thread tile: 3 i (half*24 + l8 + 8k, i=47 pad) x 4 c (l4 + 4cj).
    // MH[i][h] via PACKDUP broadcast; T1[h][c] lane-distinct scalar LDS.
    {
        float accB[3][4];
#pragma unroll
        for (int k = 0; k < 3; k++)
#pragma unroll
            for (int cj = 0; cj < 4; cj++) accB[k][cj] = 0.0f;
        const float* T1p = T1s + p*1088;
        const int ibase = half*24 + l8;
#pragma unroll 4
        for (int h = 0; h < 64; h++) {
            const float* mh = &MHs[h*48 + ibase];
            float t1v[4];
#pragma unroll
            for (int cj = 0; cj < 4; cj++) t1v[cj] = T1p[h*17 + l4 + 4*cj];
#pragma unroll
            for (int k = 0; k < 3; k++) {
                float m = mh[8*k];
#pragma unroll
                for (int cj = 0; cj < 4; cj++)
                    accB[k][cj] = __fmaf_rn(m, t1v[cj], accB[k][cj]);
            }
        }
#pragma unroll
        for (int k = 0; k < 3; k++) {
            int i = ibase + 8*k;   // 0..47; row 47 is scratch pad (T2s has 48 rows)
#pragma unroll
            for (int cj = 0; cj < 4; cj++)
                T2s[p*816 + i*17 + l4 + 4*cj] = accB[k][cj];
        }
    }
    __syncthreads();   // T2 ready

    // ---- Stage C': Y[i][j] = sum_c T2[i][c] * U_W[j][c] ----
    // thread tile: 2 i (half*24 + l8 + 8k, k<3 total 48 rows but only 47 real)
    //   x 4 j-pairs (jp = 4*l4 + q). Use 3 i like B' for uniformity.
    {
        ull accC[3][4];
#pragma unroll
        for (int k = 0; k < 3; k++)
#pragma unroll
            for (int q = 0; q < 4; q++) accC[k][q] = 0ull;
        const float* T2p = T2s + p*816;
        const int ibase = half*24 + l8;
#pragma unroll 2
        for (int c = 0; c < 16; c++) {
            ulonglong2 uw0 = *(const ulonglong2*)&UWTs[c*32 + l4*8];
            ulonglong2 uw1 = *(const ulonglong2*)&UWTs[c*32 + l4*8 + 4];
#pragma unroll
            for (int k = 0; k < 3; k++) {
                float td = T2p[(ibase + 8*k)*17 + c];
                ull tdd; PACKDUP(tdd, td);
                FFMA2(accC[k][0], tdd, uw0.x, accC[k][0]);
                FFMA2(accC[k][1], tdd, uw0.y, accC[k][1]);
                FFMA2(accC[k][2], tdd, uw1.x, accC[k][2]);
                FFMA2(accC[k][3], tdd, uw1.y, accC[k][3]);
            }
        }
        float* O = out + ((size_t)blockIdx.x*4 + p) * 1410;
#pragma unroll
        for (int k = 0; k < 3; k++) {
            int i = ibase + 8*k;
            if (i < 47) {
#pragma unroll
                for (int q = 0; q < 4; q++) {
                    int jp = 4*l4 + q;
                    if (jp < 15) {
                        float lo, hi; UNPACK2(lo, hi, accC[k][q]);
                        *(float2*)&O[i*30 + 2*jp] = make_float2(lo, hi);
                    }
                }
            }
        }
    }
}

extern "C" void kernel_launch(void* const* d_in, const int* in_sizes, int n_in,
                              void* d_out, int out_size) {
    const float* x = (const float*)d_in[0];
    float* out = (float*)d_out;
    (void)in_sizes; (void)n_in; (void)out_size;

    // Unconditional (no static guard — harness determinism rule). Idempotent,
    // non-stream API: legal during graph capture.
    cudaFuncSetAttribute(resize_main, cudaFuncAttributeMaxDynamicSharedMemorySize,
                         105728);
    build_mats<<<144, 192>>>();
    resize_main<<<2048, 256, 105728>>>(x, out);
}